// round 1
// baseline (speedup 1.0000x reference)
#include <cuda_runtime.h>

#define BATCH 8
#define SEQ   1024
#define DIM   512
#define HEADS 8
#define DHEAD 64
#define SCALE 0.125f   // 64^-0.5

#define QKV_ELEMS (BATCH*HEADS*SEQ*DHEAD)

// Scratch (device globals: allocation-free rule)
__device__ float g_q[QKV_ELEMS];
__device__ float g_k[QKV_ELEMS];
__device__ float g_v[QKV_ELEMS];
__device__ float g_o[QKV_ELEMS];

// ---------------------------------------------------------------------------
// QKV projection: Y = X @ W^T, scattered into [b, h, n, d] layout.
// Block tile 64(m) x 64(o), K-tile 16, 256 threads, 4x4 micro-tile.
// blockIdx.z selects which of {q,k,v}.
// ---------------------------------------------------------------------------
__global__ __launch_bounds__(256) void qkv_kernel(
    const float* __restrict__ X,
    const float* __restrict__ Wq,
    const float* __restrict__ Wk,
    const float* __restrict__ Wv)
{
    const float* W  = (blockIdx.z == 0) ? Wq : (blockIdx.z == 1) ? Wk : Wv;
    float*       out = (blockIdx.z == 0) ? g_q : (blockIdx.z == 1) ? g_k : g_v;

    __shared__ float As[16*64];   // [k][m]
    __shared__ float Bs[16*64];   // [k][o]

    const int m0  = blockIdx.y * 64;
    const int o0  = blockIdx.x * 64;
    const int tid = threadIdx.x;
    const int tx  = tid & 15, ty = tid >> 4;
    const int tx4 = tx << 2,  ty4 = ty << 2;
    const int lrow = tid >> 2;
    const int lq   = (tid & 3) << 2;

    const float* xp = X + (m0 + lrow) * DIM + lq;
    const float* wp = W + (o0 + lrow) * DIM + lq;

    float acc[4][4] = {};

    for (int k0 = 0; k0 < DIM; k0 += 16) {
        float4 a = *(const float4*)(xp + k0);
        float4 w = *(const float4*)(wp + k0);
        As[(lq+0)*64 + lrow] = a.x;
        As[(lq+1)*64 + lrow] = a.y;
        As[(lq+2)*64 + lrow] = a.z;
        As[(lq+3)*64 + lrow] = a.w;
        Bs[(lq+0)*64 + lrow] = w.x;
        Bs[(lq+1)*64 + lrow] = w.y;
        Bs[(lq+2)*64 + lrow] = w.z;
        Bs[(lq+3)*64 + lrow] = w.w;
        __syncthreads();
        #pragma unroll
        for (int k = 0; k < 16; k++) {
            float4 av = *(const float4*)&As[k*64 + ty4];
            float4 bv = *(const float4*)&Bs[k*64 + tx4];
            float ar[4] = {av.x, av.y, av.z, av.w};
            float br[4] = {bv.x, bv.y, bv.z, bv.w};
            #pragma unroll
            for (int r = 0; r < 4; r++)
                #pragma unroll
                for (int c = 0; c < 4; c++)
                    acc[r][c] += ar[r] * br[c];
        }
        __syncthreads();
    }

    // Scatter to [b, h, n, d]; 64-wide col-tile aligns with one head.
    const int b  = m0 >> 10;
    const int n  = m0 & 1023;
    const int hh = o0 >> 6;
    #pragma unroll
    for (int r = 0; r < 4; r++) {
        float4 v = make_float4(acc[r][0], acc[r][1], acc[r][2], acc[r][3]);
        *(float4*)&out[((size_t)(b*HEADS + hh)*SEQ + n + ty4 + r)*DHEAD + tx4] = v;
    }
}

// ---------------------------------------------------------------------------
// Attention: per (b, h, 64-row q-tile). exp(clip(S*scale)) with running
// row-sums; unnormalized PV accumulate; normalize at the end.
// smem: Qs natural [i][k], KVs (K transposed [k][j], reused as V natural
// [j][d]), Ps natural [i][j]. 3 * 16KB = 48KB static.
// ---------------------------------------------------------------------------
__global__ __launch_bounds__(256) void attn_kernel()
{
    __shared__ float Qs [64*64];
    __shared__ float KVs[64*64];
    __shared__ float Ps [64*64];

    const int qt = blockIdx.x, h = blockIdx.y, b = blockIdx.z;
    const float* Qg = g_q + ((size_t)(b*HEADS + h)*SEQ + qt*64) * DHEAD;
    const float* Kg = g_k + ((size_t)(b*HEADS + h)*SEQ) * DHEAD;
    const float* Vg = g_v + ((size_t)(b*HEADS + h)*SEQ) * DHEAD;

    const int tid = threadIdx.x;
    const int tx  = tid & 15, ty = tid >> 4;
    const int tx4 = tx << 2,  ty4 = ty << 2;

    // Load Q tile (natural layout)
    #pragma unroll
    for (int it = 0; it < 4; it++) {
        int idx = tid + it*256;
        int row = idx >> 4;
        int col = (idx & 15) << 2;
        *(float4*)&Qs[row*64 + col] = *(const float4*)&Qg[row*64 + col];
    }

    float o[4][4] = {};
    float rs[4]   = {};
    __syncthreads();

    for (int jt = 0; jt < 16; jt++) {
        // --- load K tile, transposed to [k][j] ---
        const float* Kt = Kg + jt*64*DHEAD;
        #pragma unroll
        for (int it = 0; it < 4; it++) {
            int idx = tid + it*256;
            int row = idx >> 4;
            int col = (idx & 15) << 2;
            float4 kv = *(const float4*)&Kt[row*64 + col];
            KVs[(col+0)*64 + row] = kv.x;
            KVs[(col+1)*64 + row] = kv.y;
            KVs[(col+2)*64 + row] = kv.z;
            KVs[(col+3)*64 + row] = kv.w;
        }
        __syncthreads();

        // --- S = Q K^T (64x64), 4x4 micro-tile ---
        float s[4][4] = {};
        #pragma unroll 4
        for (int k4 = 0; k4 < 64; k4 += 4) {
            float4 q0 = *(const float4*)&Qs[(ty4+0)*64 + k4];
            float4 q1 = *(const float4*)&Qs[(ty4+1)*64 + k4];
            float4 q2 = *(const float4*)&Qs[(ty4+2)*64 + k4];
            float4 q3 = *(const float4*)&Qs[(ty4+3)*64 + k4];
            float qr[4][4] = {{q0.x,q0.y,q0.z,q0.w},
                              {q1.x,q1.y,q1.z,q1.w},
                              {q2.x,q2.y,q2.z,q2.w},
                              {q3.x,q3.y,q3.z,q3.w}};
            #pragma unroll
            for (int kk = 0; kk < 4; kk++) {
                float4 kv = *(const float4*)&KVs[(k4+kk)*64 + tx4];
                float kc[4] = {kv.x, kv.y, kv.z, kv.w};
                #pragma unroll
                for (int r = 0; r < 4; r++)
                    #pragma unroll
                    for (int c = 0; c < 4; c++)
                        s[r][c] += qr[r][kk] * kc[c];
            }
        }

        // --- P = exp(clip(S*scale, 1e-6, 1)); row sums; store to smem ---
        #pragma unroll
        for (int r = 0; r < 4; r++) {
            float4 p;
            p.x = __expf(fminf(fmaxf(s[r][0]*SCALE, 1e-6f), 1.0f));
            p.y = __expf(fminf(fmaxf(s[r][1]*SCALE, 1e-6f), 1.0f));
            p.z = __expf(fminf(fmaxf(s[r][2]*SCALE, 1e-6f), 1.0f));
            p.w = __expf(fminf(fmaxf(s[r][3]*SCALE, 1e-6f), 1.0f));
            rs[r] += p.x + p.y + p.z + p.w;
            *(float4*)&Ps[(ty4+r)*64 + tx4] = p;
        }
        __syncthreads();   // Ps written; KVs (K) reads done

        // --- load V tile (natural [j][d]) into KVs ---
        const float* Vt = Vg + jt*64*DHEAD;
        #pragma unroll
        for (int it = 0; it < 4; it++) {
            int idx = tid + it*256;
            int row = idx >> 4;
            int col = (idx & 15) << 2;
            *(float4*)&KVs[row*64 + col] = *(const float4*)&Vt[row*64 + col];
        }
        __syncthreads();

        // --- O += P V ---
        #pragma unroll 4
        for (int j = 0; j < 64; j += 4) {
            float vb[4][4];
            #pragma unroll
            for (int jj = 0; jj < 4; jj++)
                *(float4*)vb[jj] = *(const float4*)&KVs[(j+jj)*64 + tx4];
            #pragma unroll
            for (int r = 0; r < 4; r++) {
                float4 pv = *(const float4*)&Ps[(ty4+r)*64 + j];
                #pragma unroll
                for (int c = 0; c < 4; c++)
                    o[r][c] += pv.x*vb[0][c] + pv.y*vb[1][c]
                             + pv.z*vb[2][c] + pv.w*vb[3][c];
            }
        }
        __syncthreads();   // KVs (V) reads done before next K load
    }

    // --- reduce row sums across tx and normalize ---
    #pragma unroll
    for (int r = 0; r < 4; r++)
        KVs[(ty4+r)*16 + tx] = rs[r];
    __syncthreads();
    #pragma unroll
    for (int r = 0; r < 4; r++) {
        float tot = 0.f;
        #pragma unroll
        for (int t = 0; t < 16; t++) tot += KVs[(ty4+r)*16 + t];
        float inv = 1.0f / tot;
        float4 v = make_float4(o[r][0]*inv, o[r][1]*inv, o[r][2]*inv, o[r][3]*inv);
        *(float4*)&g_o[((size_t)(b*HEADS + h)*SEQ + qt*64 + ty4 + r)*DHEAD + tx4] = v;
    }
}

// ---------------------------------------------------------------------------
// Output projection: out = concat_heads(O) @ Wo^T + bo.
// A is gathered from g_o's [b,h,n,d] layout (k = h*64+d).
// ---------------------------------------------------------------------------
__global__ __launch_bounds__(256) void proj_kernel(
    const float* __restrict__ Wo,
    const float* __restrict__ bo,
    float* __restrict__ out)
{
    __shared__ float As[16*64];
    __shared__ float Bs[16*64];

    const int m0  = blockIdx.y * 64;
    const int o0  = blockIdx.x * 64;
    const int tid = threadIdx.x;
    const int tx  = tid & 15, ty = tid >> 4;
    const int tx4 = tx << 2,  ty4 = ty << 2;
    const int lrow = tid >> 2;
    const int lq   = (tid & 3) << 2;

    const int b = m0 >> 10;
    const int n = (m0 & 1023) + lrow;

    const float* wp = Wo + (o0 + lrow) * DIM + lq;

    float acc[4][4] = {};

    for (int k0 = 0; k0 < DIM; k0 += 16) {
        const int hh = k0 >> 6;
        const int kk = (k0 & 63) + lq;
        float4 a = *(const float4*)&g_o[((size_t)(b*HEADS + hh)*SEQ + n)*DHEAD + kk];
        float4 w = *(const float4*)(wp + k0);
        As[(lq+0)*64 + lrow] = a.x;
        As[(lq+1)*64 + lrow] = a.y;
        As[(lq+2)*64 + lrow] = a.z;
        As[(lq+3)*64 + lrow] = a.w;
        Bs[(lq+0)*64 + lrow] = w.x;
        Bs[(lq+1)*64 + lrow] = w.y;
        Bs[(lq+2)*64 + lrow] = w.z;
        Bs[(lq+3)*64 + lrow] = w.w;
        __syncthreads();
        #pragma unroll
        for (int k = 0; k < 16; k++) {
            float4 av = *(const float4*)&As[k*64 + ty4];
            float4 bv = *(const float4*)&Bs[k*64 + tx4];
            float ar[4] = {av.x, av.y, av.z, av.w};
            float br[4] = {bv.x, bv.y, bv.z, bv.w};
            #pragma unroll
            for (int r = 0; r < 4; r++)
                #pragma unroll
                for (int c = 0; c < 4; c++)
                    acc[r][c] += ar[r] * br[c];
        }
        __syncthreads();
    }

    float4 bias = *(const float4*)&bo[o0 + tx4];
    float bb[4] = {bias.x, bias.y, bias.z, bias.w};
    #pragma unroll
    for (int r = 0; r < 4; r++) {
        float4 v = make_float4(acc[r][0]+bb[0], acc[r][1]+bb[1],
                               acc[r][2]+bb[2], acc[r][3]+bb[3]);
        *(float4*)&out[(size_t)(m0 + ty4 + r)*DIM + o0 + tx4] = v;
    }
}

// ---------------------------------------------------------------------------
extern "C" void kernel_launch(void* const* d_in, const int* in_sizes, int n_in,
                              void* d_out, int out_size)
{
    (void)in_sizes; (void)n_in; (void)out_size;
    const float* x  = (const float*)d_in[0];
    const float* wq = (const float*)d_in[1];
    const float* wk = (const float*)d_in[2];
    const float* wv = (const float*)d_in[3];
    const float* wo = (const float*)d_in[4];
    const float* bo = (const float*)d_in[5];
    float* out = (float*)d_out;

    qkv_kernel<<<dim3(8, 128, 3), 256>>>(x, wq, wk, wv);
    attn_kernel<<<dim3(16, HEADS, BATCH), 256>>>();
    proj_kernel<<<dim3(8, 128), 256>>>(wo, bo, out);
}

// round 3
// speedup vs baseline: 1.4797x; 1.4797x over previous
#include <cuda_runtime.h>
#include <cstdint>

#define BATCH 8
#define SEQ   1024
#define DIM   512
#define HEADS 8
#define DHEAD 64
#define SCALE 0.125f

#define QKV_ELEMS (BATCH*HEADS*SEQ*DHEAD)

__device__ float g_q[QKV_ELEMS];
__device__ float g_k[QKV_ELEMS];
__device__ float g_v[QKV_ELEMS];
__device__ float g_o[QKV_ELEMS];

// Round-to-nearest tf32 bit pattern.
__device__ __forceinline__ uint32_t rtf_u(float x) {
    uint32_t u = __float_as_uint(x);
    return (u + 0x1000u) & 0xFFFFE000u;
}

// m16n8k8 tf32 HMMA, D=C accumulate in fp32.
__device__ __forceinline__ void mma1688(float c[4],
                                        uint32_t a0, uint32_t a1, uint32_t a2, uint32_t a3,
                                        uint32_t b0, uint32_t b1) {
    asm volatile(
        "mma.sync.aligned.m16n8k8.row.col.f32.tf32.tf32.f32 "
        "{%0,%1,%2,%3}, {%4,%5,%6,%7}, {%8,%9}, {%0,%1,%2,%3};\n"
        : "+f"(c[0]), "+f"(c[1]), "+f"(c[2]), "+f"(c[3])
        : "r"(a0), "r"(a1), "r"(a2), "r"(a3), "r"(b0), "r"(b1));
}

// ===========================================================================
// Fragment-major smem layouts.
// A (m16k8 tile): 128 u32/tile, thread t's 4 regs at t*4+reg.
//   elem(r,c): t=(r&7)*4+(c&3), reg=(r>>3) | ((c>>2)<<1)
// B (n8k8 tile): 64 u32/tile, thread t's 2 regs at t*2+reg.
//   elem(n,k): t=n*4+(k&3), reg=k>>2
// ===========================================================================

// ---------------------------------------------------------------------------
// QKV: C = X @ W^T scattered to [b,h,n,d]. CTA tile 128(m) x 64(n=1 head),
// 256 threads (8 warps: 4m x 2n, warp 32x32), K-block 32, double buffered.
// ---------------------------------------------------------------------------
__global__ __launch_bounds__(256) void qkv_tc(
    const float* __restrict__ X, const float* __restrict__ Wq,
    const float* __restrict__ Wk, const float* __restrict__ Wv)
{
    __shared__ uint32_t sA[2][4096];   // 8 m-tiles x 4 k-tiles x 128
    __shared__ uint32_t sB[2][2048];   // 8 n-tiles x 4 k-tiles x 64

    const int tid = threadIdx.x, lane = tid & 31, wid = tid >> 5;
    const int z = blockIdx.z, h = blockIdx.x, m0 = blockIdx.y * 128;
    const float* W  = (z == 0) ? Wq : (z == 1) ? Wk : Wv;
    float* out = (z == 0) ? g_q : (z == 1) ? g_k : g_v;

    const int arow = tid >> 1, ahalf = tid & 1;
    const int brow = tid >> 2, bq = tid & 3;
    const float* Ag = X + (size_t)(m0 + arow) * DIM + ahalf * 16;
    const float* Bg = W + (size_t)(h * 64 + brow) * DIM + bq * 8;

    const int a_im = arow >> 4, a_rr = arow & 15;
    const int a_tb = (a_rr & 7) * 4, a_rb = a_rr >> 3;
    const int b_in = brow >> 3, b_tb = (brow & 7) * 4;

    float4 pa[4]; float4 pb[2];
    #pragma unroll
    for (int q = 0; q < 4; q++) pa[q] = *(const float4*)(Ag + q * 4);
    #pragma unroll
    for (int q = 0; q < 2; q++) pb[q] = *(const float4*)(Bg + q * 4);

    // store prefetch regs -> buffer
    auto stash = [&](int buf) {
        #pragma unroll
        for (int q = 0; q < 4; q++) {
            float e[4] = {pa[q].x, pa[q].y, pa[q].z, pa[q].w};
            #pragma unroll
            for (int i = 0; i < 4; i++) {
                int cf = ahalf * 16 + q * 4 + i;
                int ik = cf >> 3, cc = cf & 7;
                sA[buf][(a_im * 4 + ik) * 128 + (a_tb + (cc & 3)) * 4
                        + (a_rb | ((cc >> 2) << 1))] = rtf_u(e[i]);
            }
        }
        #pragma unroll
        for (int q = 0; q < 2; q++) {
            float e[4] = {pb[q].x, pb[q].y, pb[q].z, pb[q].w};
            #pragma unroll
            for (int i = 0; i < 4; i++) {
                int cf = bq * 8 + q * 4 + i;
                int ik = cf >> 3, cc = cf & 7;
                sB[buf][(b_in * 4 + ik) * 64 + (b_tb + (cc & 3)) * 2 + (cc >> 2)]
                    = rtf_u(e[i]);
            }
        }
    };

    stash(0);
    __syncthreads();

    float acc[2][4][4] = {};
    const int wm = wid >> 1, wn = wid & 1;

    for (int kt = 0; kt < 16; kt++) {
        const int cur = kt & 1;
        if (kt < 15) {
            #pragma unroll
            for (int q = 0; q < 4; q++) pa[q] = *(const float4*)(Ag + (kt + 1) * 32 + q * 4);
            #pragma unroll
            for (int q = 0; q < 2; q++) pb[q] = *(const float4*)(Bg + (kt + 1) * 32 + q * 4);
        }
        #pragma unroll
        for (int ik = 0; ik < 4; ik++) {
            uint4 a[2];
            a[0] = *(const uint4*)&sA[cur][((wm * 2 + 0) * 4 + ik) * 128 + lane * 4];
            a[1] = *(const uint4*)&sA[cur][((wm * 2 + 1) * 4 + ik) * 128 + lane * 4];
            uint2 b[4];
            #pragma unroll
            for (int in = 0; in < 4; in++)
                b[in] = *(const uint2*)&sB[cur][((wn * 4 + in) * 4 + ik) * 64 + lane * 2];
            #pragma unroll
            for (int im = 0; im < 2; im++)
                #pragma unroll
                for (int in = 0; in < 4; in++)
                    mma1688(acc[im][in], a[im].x, a[im].y, a[im].z, a[im].w,
                            b[in].x, b[in].y);
        }
        if (kt < 15) { stash((kt + 1) & 1); __syncthreads(); }
    }

    // epilogue: scatter to [b,h,n,d]
    const int g = lane >> 2, tg = lane & 3;
    #pragma unroll
    for (int im = 0; im < 2; im++) {
        #pragma unroll
        for (int in = 0; in < 4; in++) {
            int m = m0 + wm * 32 + im * 16 + g;
            int b = m >> 10, ns = m & 1023;
            int d = wn * 32 + in * 8 + tg * 2;
            float* op = out + ((size_t)(b * HEADS + h) * SEQ + ns) * DHEAD + d;
            *(float2*)op = make_float2(acc[im][in][0], acc[im][in][1]);
            *(float2*)(op + 8 * DHEAD) = make_float2(acc[im][in][2], acc[im][in][3]);
        }
    }
}

// ---------------------------------------------------------------------------
// Attention: CTA per (qt, h, b): 64 q-rows, 128 threads (4 warps, warp=16 q).
// Per 64-kv tile: S=QK^T (frag regs) -> exp(clip) -> PV with A from shuffles.
// ---------------------------------------------------------------------------
__global__ __launch_bounds__(128) void attn_tc()
{
    __shared__ uint32_t sQ[4096];   // 4 m-tiles x 8 k-tiles x 128 (A layout)
    __shared__ uint32_t sK[4096];   // 8 n-tiles x 8 k-tiles x 64  (B layout)
    __shared__ uint32_t sV[4096];   // 8 n(d)-tiles x 8 k(j)-tiles x 64 (B layout)

    const int tid = threadIdx.x, lane = tid & 31, wid = tid >> 5;
    const int qt = blockIdx.x, h = blockIdx.y, b = blockIdx.z;
    const float* Qg = g_q + ((size_t)(b * HEADS + h) * SEQ + qt * 64) * DHEAD;
    const float* Kg = g_k + ((size_t)(b * HEADS + h) * SEQ) * DHEAD;
    const float* Vg = g_v + ((size_t)(b * HEADS + h) * SEQ) * DHEAD;

    const int row = tid >> 1, half = tid & 1;
    const int q_im = row >> 4, q_rr = row & 15;
    const int q_tb = (q_rr & 7) * 4, q_rb = q_rr >> 3;
    const int k_in = row >> 3, k_tb = (row & 7) * 4;
    const int v_ik = row >> 3, v_tp = row & 3, v_reg = (row >> 2) & 1;

    // Q fill (once)
    {
        const float* qp = Qg + (size_t)row * DHEAD + half * 32;
        #pragma unroll
        for (int q = 0; q < 8; q++) {
            float4 v = *(const float4*)(qp + q * 4);
            float e[4] = {v.x, v.y, v.z, v.w};
            #pragma unroll
            for (int i = 0; i < 4; i++) {
                int cf = half * 32 + q * 4 + i;
                int ik = cf >> 3, cc = cf & 7;
                sQ[(q_im * 8 + ik) * 128 + (q_tb + (cc & 3)) * 4
                   + (q_rb | ((cc >> 2) << 1))] = rtf_u(e[i]);
            }
        }
    }

    float oc[8][4] = {};
    float rsum0 = 0.f, rsum1 = 0.f;
    const int tg = lane & 3;
    const int src1 = (lane & ~3) | (tg >> 1);
    const int src2 = src1 + 2;
    const bool sel = tg & 1;

    for (int t = 0; t < 16; t++) {
        __syncthreads();   // previous compute done reading sK/sV
        // K tile fill (row j = row)
        {
            const float* kp = Kg + (size_t)(t * 64 + row) * DHEAD + half * 32;
            #pragma unroll
            for (int q = 0; q < 8; q++) {
                float4 v = *(const float4*)(kp + q * 4);
                float e[4] = {v.x, v.y, v.z, v.w};
                #pragma unroll
                for (int i = 0; i < 4; i++) {
                    int cf = half * 32 + q * 4 + i;
                    int ik = cf >> 3, cc = cf & 7;
                    sK[(k_in * 8 + ik) * 64 + (k_tb + (cc & 3)) * 2 + (cc >> 2)]
                        = rtf_u(e[i]);
                }
            }
        }
        // V tile fill (k=j=row, n=d)
        {
            const float* vp = Vg + (size_t)(t * 64 + row) * DHEAD + half * 32;
            #pragma unroll
            for (int q = 0; q < 8; q++) {
                float4 v = *(const float4*)(vp + q * 4);
                float e[4] = {v.x, v.y, v.z, v.w};
                #pragma unroll
                for (int i = 0; i < 4; i++) {
                    int d = half * 32 + q * 4 + i;
                    sV[((d >> 3) * 8 + v_ik) * 64 + ((d & 7) * 4 + v_tp) * 2 + v_reg]
                        = rtf_u(e[i]);
                }
            }
        }
        __syncthreads();

        // S = Q K^T : warp wid owns q-rows [wid*16, wid*16+16)
        float sc[8][4] = {};
        #pragma unroll
        for (int ik = 0; ik < 8; ik++) {
            uint4 a = *(const uint4*)&sQ[(wid * 8 + ik) * 128 + lane * 4];
            #pragma unroll
            for (int in = 0; in < 8; in++) {
                uint2 bb = *(const uint2*)&sK[(in * 8 + ik) * 64 + lane * 2];
                mma1688(sc[in], a.x, a.y, a.z, a.w, bb.x, bb.y);
            }
        }

        // P = exp(clip(S*scale)) + running row sums
        #pragma unroll
        for (int in = 0; in < 8; in++) {
            #pragma unroll
            for (int r = 0; r < 4; r++)
                sc[in][r] = __expf(fminf(fmaxf(sc[in][r] * SCALE, 1e-6f), 1.0f));
            rsum0 += sc[in][0] + sc[in][1];
            rsum1 += sc[in][2] + sc[in][3];
        }

        // O += P V  (A frags rebuilt from sc via quad shuffles)
        #pragma unroll
        for (int ik = 0; ik < 8; ik++) {
            float p0 = sc[ik][0], p1 = sc[ik][1], p2 = sc[ik][2], p3 = sc[ik][3];
            float v00 = __shfl_sync(0xffffffffu, p0, src1);
            float v01 = __shfl_sync(0xffffffffu, p1, src1);
            float v10 = __shfl_sync(0xffffffffu, p2, src1);
            float v11 = __shfl_sync(0xffffffffu, p3, src1);
            float v20 = __shfl_sync(0xffffffffu, p0, src2);
            float v21 = __shfl_sync(0xffffffffu, p1, src2);
            float v30 = __shfl_sync(0xffffffffu, p2, src2);
            float v31 = __shfl_sync(0xffffffffu, p3, src2);
            uint32_t a0 = rtf_u(sel ? v01 : v00);
            uint32_t a1 = rtf_u(sel ? v11 : v10);
            uint32_t a2 = rtf_u(sel ? v21 : v20);
            uint32_t a3 = rtf_u(sel ? v31 : v30);
            #pragma unroll
            for (int in = 0; in < 8; in++) {
                uint2 bb = *(const uint2*)&sV[(in * 8 + ik) * 64 + lane * 2];
                mma1688(oc[in], a0, a1, a2, a3, bb.x, bb.y);
            }
        }
    }

    // row-sum reduce over quad (cols split across tg)
    rsum0 += __shfl_xor_sync(0xffffffffu, rsum0, 1);
    rsum0 += __shfl_xor_sync(0xffffffffu, rsum0, 2);
    rsum1 += __shfl_xor_sync(0xffffffffu, rsum1, 1);
    rsum1 += __shfl_xor_sync(0xffffffffu, rsum1, 2);
    const float inv0 = 1.0f / rsum0, inv1 = 1.0f / rsum1;

    const int g = lane >> 2;
    const int m = qt * 64 + wid * 16 + g;
    float* ob = g_o + ((size_t)(b * HEADS + h) * SEQ + m) * DHEAD;
    #pragma unroll
    for (int in = 0; in < 8; in++) {
        int d = in * 8 + tg * 2;
        *(float2*)(ob + d) = make_float2(oc[in][0] * inv0, oc[in][1] * inv0);
        *(float2*)(ob + 8 * DHEAD + d) = make_float2(oc[in][2] * inv1, oc[in][3] * inv1);
    }
}

// ---------------------------------------------------------------------------
// Out-proj: out = concat(g_o) @ Wo^T + bo. CTA tile 128 x 64, like qkv_tc
// but A gathered from [b,h,n,d] and bias-add epilogue.
// ---------------------------------------------------------------------------
__global__ __launch_bounds__(256) void proj_tc(
    const float* __restrict__ Wo, const float* __restrict__ bo,
    float* __restrict__ outp)
{
    __shared__ uint32_t sA[2][4096];
    __shared__ uint32_t sB[2][2048];

    const int tid = threadIdx.x, lane = tid & 31, wid = tid >> 5;
    const int nx = blockIdx.x, m0 = blockIdx.y * 128;
    const int bb = m0 >> 10, nsb = m0 & 1023;

    const int arow = tid >> 1, ahalf = tid & 1;
    const int brow = tid >> 2, bq = tid & 3;
    const float* Bg = Wo + (size_t)(nx * 64 + brow) * DIM + bq * 8;

    const int a_im = arow >> 4, a_rr = arow & 15;
    const int a_tb = (a_rr & 7) * 4, a_rb = a_rr >> 3;
    const int b_in = brow >> 3, b_tb = (brow & 7) * 4;

    auto aptr = [&](int kt) {
        return g_o + ((size_t)(bb * HEADS + (kt >> 1)) * SEQ + nsb + arow) * DHEAD
               + (kt & 1) * 32 + ahalf * 16;
    };

    float4 pa[4]; float4 pb[2];
    {
        const float* ap = aptr(0);
        #pragma unroll
        for (int q = 0; q < 4; q++) pa[q] = *(const float4*)(ap + q * 4);
        #pragma unroll
        for (int q = 0; q < 2; q++) pb[q] = *(const float4*)(Bg + q * 4);
    }

    auto stash = [&](int buf) {
        #pragma unroll
        for (int q = 0; q < 4; q++) {
            float e[4] = {pa[q].x, pa[q].y, pa[q].z, pa[q].w};
            #pragma unroll
            for (int i = 0; i < 4; i++) {
                int cf = ahalf * 16 + q * 4 + i;
                int ik = cf >> 3, cc = cf & 7;
                sA[buf][(a_im * 4 + ik) * 128 + (a_tb + (cc & 3)) * 4
                        + (a_rb | ((cc >> 2) << 1))] = rtf_u(e[i]);
            }
        }
        #pragma unroll
        for (int q = 0; q < 2; q++) {
            float e[4] = {pb[q].x, pb[q].y, pb[q].z, pb[q].w};
            #pragma unroll
            for (int i = 0; i < 4; i++) {
                int cf = bq * 8 + q * 4 + i;
                int ik = cf >> 3, cc = cf & 7;
                sB[buf][(b_in * 4 + ik) * 64 + (b_tb + (cc & 3)) * 2 + (cc >> 2)]
                    = rtf_u(e[i]);
            }
        }
    };

    stash(0);
    __syncthreads();

    float acc[2][4][4] = {};
    const int wm = wid >> 1, wn = wid & 1;

    for (int kt = 0; kt < 16; kt++) {
        const int cur = kt & 1;
        if (kt < 15) {
            const float* ap = aptr(kt + 1);
            #pragma unroll
            for (int q = 0; q < 4; q++) pa[q] = *(const float4*)(ap + q * 4);
            #pragma unroll
            for (int q = 0; q < 2; q++) pb[q] = *(const float4*)(Bg + (kt + 1) * 32 + q * 4);
        }
        #pragma unroll
        for (int ik = 0; ik < 4; ik++) {
            uint4 a[2];
            a[0] = *(const uint4*)&sA[cur][((wm * 2 + 0) * 4 + ik) * 128 + lane * 4];
            a[1] = *(const uint4*)&sA[cur][((wm * 2 + 1) * 4 + ik) * 128 + lane * 4];
            uint2 b[4];
            #pragma unroll
            for (int in = 0; in < 4; in++)
                b[in] = *(const uint2*)&sB[cur][((wn * 4 + in) * 4 + ik) * 64 + lane * 2];
            #pragma unroll
            for (int im = 0; im < 2; im++)
                #pragma unroll
                for (int in = 0; in < 4; in++)
                    mma1688(acc[im][in], a[im].x, a[im].y, a[im].z, a[im].w,
                            b[in].x, b[in].y);
        }
        if (kt < 15) { stash((kt + 1) & 1); __syncthreads(); }
    }

    const int g = lane >> 2, tg = lane & 3;
    #pragma unroll
    for (int im = 0; im < 2; im++) {
        #pragma unroll
        for (int in = 0; in < 4; in++) {
            int m = m0 + wm * 32 + im * 16 + g;
            int d = wn * 32 + in * 8 + tg * 2;
            float2 bias = *(const float2*)(bo + nx * 64 + d);
            float* op = outp + (size_t)m * DIM + nx * 64 + d;
            *(float2*)op = make_float2(acc[im][in][0] + bias.x, acc[im][in][1] + bias.y);
            *(float2*)(op + 8 * DIM) = make_float2(acc[im][in][2] + bias.x,
                                                   acc[im][in][3] + bias.y);
        }
    }
}

// ---------------------------------------------------------------------------
extern "C" void kernel_launch(void* const* d_in, const int* in_sizes, int n_in,
                              void* d_out, int out_size)
{
    (void)in_sizes; (void)n_in; (void)out_size;
    const float* x  = (const float*)d_in[0];
    const float* wq = (const float*)d_in[1];
    const float* wk = (const float*)d_in[2];
    const float* wv = (const float*)d_in[3];
    const float* wo = (const float*)d_in[4];
    const float* bo = (const float*)d_in[5];
    float* out = (float*)d_out;

    qkv_tc<<<dim3(HEADS, 64, 3), 256>>>(x, wq, wk, wv);
    attn_tc<<<dim3(16, HEADS, BATCH), 128>>>();
    proj_tc<<<dim3(DIM / 64, 64), 256>>>(wo, bo, out);
}

// round 4
// speedup vs baseline: 2.2196x; 1.5001x over previous
#include <cuda_runtime.h>
#include <cstdint>

#define BATCH 8
#define SEQ   1024
#define DIM   512
#define HEADS 8
#define DHEAD 64
#define SCALE 0.125f

#define QKV_ELEMS (BATCH*HEADS*SEQ*DHEAD)

__device__ float g_q[QKV_ELEMS];
__device__ float g_k[QKV_ELEMS];
__device__ float g_v[QKV_ELEMS];
__device__ float g_o[QKV_ELEMS];

// Round-to-nearest tf32 bit pattern.
__device__ __forceinline__ uint32_t rtf_u(float x) {
    uint32_t u = __float_as_uint(x);
    return (u + 0x1000u) & 0xFFFFE000u;
}
__device__ __forceinline__ uint4 rtf4_u(float4 v) {
    return make_uint4(rtf_u(v.x), rtf_u(v.y), rtf_u(v.z), rtf_u(v.w));
}

__device__ __forceinline__ uint32_t smem_u32(const void* p) {
    uint32_t a;
    asm("{ .reg .u64 t; cvta.to.shared.u64 t, %1; cvt.u32.u64 %0, t; }" : "=r"(a) : "l"(p));
    return a;
}

// m16n8k8 tf32 HMMA, fp32 accumulate.
__device__ __forceinline__ void mma1688(float c[4],
                                        uint32_t a0, uint32_t a1, uint32_t a2, uint32_t a3,
                                        uint32_t b0, uint32_t b1) {
    asm volatile(
        "mma.sync.aligned.m16n8k8.row.col.f32.tf32.tf32.f32 "
        "{%0,%1,%2,%3}, {%4,%5,%6,%7}, {%8,%9}, {%0,%1,%2,%3};\n"
        : "+f"(c[0]), "+f"(c[1]), "+f"(c[2]), "+f"(c[3])
        : "r"(a0), "r"(a1), "r"(a2), "r"(a3), "r"(b0), "r"(b1));
}

#define LDSM_X4(d0, d1, d2, d3, addr) \
    asm volatile("ldmatrix.sync.aligned.m8n8.x4.shared.b16 {%0,%1,%2,%3}, [%4];" \
                 : "=r"(d0), "=r"(d1), "=r"(d2), "=r"(d3) : "r"(addr))

// ===========================================================================
// QKV: C = X @ W^T scattered to [b,h,n,d]. CTA tile 128(m) x 64(n=1 head),
// 256 thr (8 warps: 4m x 2n, warp 32x32), K-block 32, double buffered smem.
// smem rows are 32 floats (128B), chunk-XOR swizzled; frags via ldmatrix.
// ===========================================================================
__global__ __launch_bounds__(256) void qkv_tc(
    const float* __restrict__ X, const float* __restrict__ Wq,
    const float* __restrict__ Wk, const float* __restrict__ Wv)
{
    __shared__ __align__(16) uint32_t sA[2][4096];   // 128 rows x 32
    __shared__ __align__(16) uint32_t sB[2][2048];   // 64 rows x 32

    const int tid = threadIdx.x, lane = tid & 31, wid = tid >> 5;
    const int z = blockIdx.z, h = blockIdx.x, m0 = blockIdx.y * 128;
    const float* W  = (z == 0) ? Wq : (z == 1) ? Wk : Wv;
    float* out = (z == 0) ? g_q : (z == 1) ? g_k : g_v;

    const int arow = tid >> 1, ahalf = tid & 1;     // A: 2 thr/row, 16 floats
    const int brow = tid >> 2, bq = tid & 3;        // B: 4 thr/row, 8 floats
    const float* Ag = X + (size_t)(m0 + arow) * DIM + ahalf * 16;
    const float* Bg = W + (size_t)(h * 64 + brow) * DIM + bq * 8;

    float4 pa[4], pb[2];
    #pragma unroll
    for (int q = 0; q < 4; q++) pa[q] = *(const float4*)(Ag + q * 4);
    #pragma unroll
    for (int q = 0; q < 2; q++) pb[q] = *(const float4*)(Bg + q * 4);

    auto stash = [&](int buf) {
        #pragma unroll
        for (int q = 0; q < 4; q++) {
            int c = ahalf * 4 + q;
            *(uint4*)&sA[buf][arow * 32 + ((c ^ (arow & 7)) << 2)] = rtf4_u(pa[q]);
        }
        #pragma unroll
        for (int q = 0; q < 2; q++) {
            int c = bq * 2 + q;
            *(uint4*)&sB[buf][brow * 32 + ((c ^ (brow & 7)) << 2)] = rtf4_u(pb[q]);
        }
    };

    stash(0);
    __syncthreads();

    const int wm = wid >> 1, wn = wid & 1;
    const uint32_t sAb = smem_u32(sA), sBb = smem_u32(sB);
    const int lx = lane & 7;
    // A frag addr: row = wm*32 + im*16 + (lane&15), chunk = 2ik + (lane>>4)
    const uint32_t aBase = sAb + (uint32_t)(wm * 32 + (lane & 15)) * 128;
    const int aCsel = lane >> 4;
    // B frag addr (x4 over n-tile pair): row = wn*32 + in2*16 + (lane>>4)*8 + lx
    const uint32_t bBase = sBb + (uint32_t)(wn * 32 + ((lane >> 4) << 3) + lx) * 128;
    const int bCsel = (lane >> 3) & 1;

    float acc[2][4][4] = {};

    for (int kt = 0; kt < 16; kt++) {
        const int cur = kt & 1;
        if (kt < 15) {
            #pragma unroll
            for (int q = 0; q < 4; q++) pa[q] = *(const float4*)(Ag + (kt + 1) * 32 + q * 4);
            #pragma unroll
            for (int q = 0; q < 2; q++) pb[q] = *(const float4*)(Bg + (kt + 1) * 32 + q * 4);
        }
        #pragma unroll
        for (int ik = 0; ik < 4; ik++) {
            uint32_t a[2][4];
            #pragma unroll
            for (int im = 0; im < 2; im++) {
                uint32_t ad = aBase + cur * 16384 + im * 2048
                            + (uint32_t)(((2 * ik + aCsel) ^ lx) << 4);
                LDSM_X4(a[im][0], a[im][1], a[im][2], a[im][3], ad);
            }
            uint32_t b[4][2];
            #pragma unroll
            for (int in2 = 0; in2 < 2; in2++) {
                uint32_t bd = bBase + cur * 8192 + in2 * 2048
                            + (uint32_t)(((2 * ik + bCsel) ^ lx) << 4);
                uint32_t r0, r1, r2, r3;
                LDSM_X4(r0, r1, r2, r3, bd);
                b[in2*2][0] = r0; b[in2*2][1] = r1;
                b[in2*2+1][0] = r2; b[in2*2+1][1] = r3;
            }
            #pragma unroll
            for (int im = 0; im < 2; im++)
                #pragma unroll
                for (int in = 0; in < 4; in++)
                    mma1688(acc[im][in], a[im][0], a[im][1], a[im][2], a[im][3],
                            b[in][0], b[in][1]);
        }
        if (kt < 15) { __syncthreads(); stash((kt + 1) & 1); __syncthreads(); }
    }

    const int g = lane >> 2, tg = lane & 3;
    #pragma unroll
    for (int im = 0; im < 2; im++) {
        #pragma unroll
        for (int in = 0; in < 4; in++) {
            int m = m0 + wm * 32 + im * 16 + g;
            int b = m >> 10, ns = m & 1023;
            int d = wn * 32 + in * 8 + tg * 2;
            float* op = out + ((size_t)(b * HEADS + h) * SEQ + ns) * DHEAD + d;
            *(float2*)op = make_float2(acc[im][in][0], acc[im][in][1]);
            *(float2*)(op + 8 * DHEAD) = make_float2(acc[im][in][2], acc[im][in][3]);
        }
    }
}

// ===========================================================================
// Attention: CTA per (qt, h, b): 64 q-rows, 128 thr (4 warps, warp = 16 q).
// Q frags hoisted to regs; K and V^T in 256B-row swizzled smem, ldmatrix.
// ===========================================================================
__global__ __launch_bounds__(128) void attn_tc()
{
    __shared__ __align__(16) uint32_t sQ[4096];   // 64 rows x 64 (d)
    __shared__ __align__(16) uint32_t sK[4096];   // 64 rows (j) x 64 (d)
    __shared__ __align__(16) uint32_t sV[4096];   // 64 rows (d) x 64 (j)  (V^T)

    const int tid = threadIdx.x, lane = tid & 31, wid = tid >> 5;
    const int qt = blockIdx.x, h = blockIdx.y, b = blockIdx.z;
    const float* Qg = g_q + ((size_t)(b * HEADS + h) * SEQ + qt * 64) * DHEAD;
    const float* Kg = g_k + ((size_t)(b * HEADS + h) * SEQ) * DHEAD;
    const float* Vg = g_v + ((size_t)(b * HEADS + h) * SEQ) * DHEAD;

    const int row = tid >> 1, half = tid & 1;   // 2 thr/row, 32 floats each
    // 16-chunk swizzle for 256B rows: c' = ((c&7)^(r&7)) | (c&8)
    #define SW16(r, c) ((((c) & 7) ^ ((r) & 7)) | ((c) & 8))

    // ---- Q fill ----
    {
        const float* qp = Qg + (size_t)row * DHEAD + half * 32;
        #pragma unroll
        for (int q = 0; q < 8; q++) {
            int c = half * 8 + q;
            *(uint4*)&sQ[row * 64 + (SW16(row, c) << 2)] = rtf4_u(*(const float4*)(qp + q * 4));
        }
    }
    __syncthreads();

    const uint32_t sQb = smem_u32(sQ), sKb = smem_u32(sK), sVb = smem_u32(sV);
    const int lx = lane & 7;
    const int aCsel = lane >> 4;              // A frag chunk select
    const int bCsel = (lane >> 3) & 1;        // B frag chunk select

    // ---- hoist Q fragments: warp wid owns q-rows wid*16.. ----
    uint32_t qf[8][4];
    {
        const int qrow = wid * 16 + (lane & 15);
        const uint32_t qBase = sQb + (uint32_t)qrow * 256;
        #pragma unroll
        for (int ik = 0; ik < 8; ik++) {
            uint32_t ad = qBase + (uint32_t)(SW16(qrow, 2 * ik + aCsel) << 4);
            LDSM_X4(qf[ik][0], qf[ik][1], qf[ik][2], qf[ik][3], ad);
        }
    }

    // B frag row bases (16 rows per x4 pair)
    const int bRowOff = ((lane >> 4) << 3) + lx;
    const uint32_t kBase = sKb + (uint32_t)bRowOff * 256;
    const uint32_t vBase = sVb + (uint32_t)bRowOff * 256;
    const int bSwz = bRowOff & 7;   // == lx

    float oc[8][4] = {};
    float rsum0 = 0.f, rsum1 = 0.f;
    const int tg = lane & 3;
    const int src1 = (lane & ~3) | (tg >> 1);
    const int src2 = src1 + 2;
    const bool sel = tg & 1;

    for (int t = 0; t < 16; t++) {
        if (t) __syncthreads();
        // ---- K fill (row j = row) ----
        {
            const float* kp = Kg + (size_t)(t * 64 + row) * DHEAD + half * 32;
            #pragma unroll
            for (int q = 0; q < 8; q++) {
                int c = half * 8 + q;
                *(uint4*)&sK[row * 64 + (SW16(row, c) << 2)] =
                    rtf4_u(*(const float4*)(kp + q * 4));
            }
        }
        // ---- V^T fill: (row=d, col=j) ----
        {
            const float* vp = Vg + (size_t)(t * 64 + row) * DHEAD + half * 32;
            const int j = row;
            #pragma unroll
            for (int q = 0; q < 8; q++) {
                uint4 v = rtf4_u(*(const float4*)(vp + q * 4));
                uint32_t e[4] = {v.x, v.y, v.z, v.w};
                #pragma unroll
                for (int i = 0; i < 4; i++) {
                    int d = half * 32 + q * 4 + i;
                    sV[d * 64 + (SW16(d, j >> 2) << 2) + (j & 3)] = e[i];
                }
            }
        }
        __syncthreads();

        // ---- S = Q K^T ----
        float sc[8][4] = {};
        #pragma unroll
        for (int ik = 0; ik < 8; ik++) {
            #pragma unroll
            for (int in2 = 0; in2 < 4; in2++) {
                uint32_t bd = kBase + in2 * 4096
                            + (uint32_t)((((2 * ik + bCsel) & 7) ^ bSwz
                                          | ((2 * ik + bCsel) & 8)) << 4);
                uint32_t r0, r1, r2, r3;
                LDSM_X4(r0, r1, r2, r3, bd);
                mma1688(sc[in2 * 2],     qf[ik][0], qf[ik][1], qf[ik][2], qf[ik][3], r0, r1);
                mma1688(sc[in2 * 2 + 1], qf[ik][0], qf[ik][1], qf[ik][2], qf[ik][3], r2, r3);
            }
        }

        // ---- P = exp(clip(S*scale)), running row sums ----
        #pragma unroll
        for (int in = 0; in < 8; in++) {
            #pragma unroll
            for (int r = 0; r < 4; r++)
                sc[in][r] = __expf(fminf(fmaxf(sc[in][r] * SCALE, 1e-6f), 1.0f));
            rsum0 += sc[in][0] + sc[in][1];
            rsum1 += sc[in][2] + sc[in][3];
        }

        // ---- O += P V (A frags rebuilt via quad shuffles) ----
        #pragma unroll
        for (int ik = 0; ik < 8; ik++) {
            float p0 = sc[ik][0], p1 = sc[ik][1], p2 = sc[ik][2], p3 = sc[ik][3];
            float v00 = __shfl_sync(0xffffffffu, p0, src1);
            float v01 = __shfl_sync(0xffffffffu, p1, src1);
            float v10 = __shfl_sync(0xffffffffu, p2, src1);
            float v11 = __shfl_sync(0xffffffffu, p3, src1);
            float v20 = __shfl_sync(0xffffffffu, p0, src2);
            float v21 = __shfl_sync(0xffffffffu, p1, src2);
            float v30 = __shfl_sync(0xffffffffu, p2, src2);
            float v31 = __shfl_sync(0xffffffffu, p3, src2);
            uint32_t a0 = rtf_u(sel ? v01 : v00);
            uint32_t a1 = rtf_u(sel ? v11 : v10);
            uint32_t a2 = rtf_u(sel ? v21 : v20);
            uint32_t a3 = rtf_u(sel ? v31 : v30);
            #pragma unroll
            for (int in2 = 0; in2 < 4; in2++) {
                uint32_t bd = vBase + in2 * 4096
                            + (uint32_t)((((2 * ik + bCsel) & 7) ^ bSwz
                                          | ((2 * ik + bCsel) & 8)) << 4);
                uint32_t r0, r1, r2, r3;
                LDSM_X4(r0, r1, r2, r3, bd);
                mma1688(oc[in2 * 2],     a0, a1, a2, a3, r0, r1);
                mma1688(oc[in2 * 2 + 1], a0, a1, a2, a3, r2, r3);
            }
        }
    }

    rsum0 += __shfl_xor_sync(0xffffffffu, rsum0, 1);
    rsum0 += __shfl_xor_sync(0xffffffffu, rsum0, 2);
    rsum1 += __shfl_xor_sync(0xffffffffu, rsum1, 1);
    rsum1 += __shfl_xor_sync(0xffffffffu, rsum1, 2);
    const float inv0 = 1.0f / rsum0, inv1 = 1.0f / rsum1;

    const int g = lane >> 2;
    const int m = qt * 64 + wid * 16 + g;
    float* ob = g_o + ((size_t)(b * HEADS + h) * SEQ + m) * DHEAD;
    #pragma unroll
    for (int in = 0; in < 8; in++) {
        int d = in * 8 + tg * 2;
        *(float2*)(ob + d) = make_float2(oc[in][0] * inv0, oc[in][1] * inv0);
        *(float2*)(ob + 8 * DHEAD + d) = make_float2(oc[in][2] * inv1, oc[in][3] * inv1);
    }
}

// ===========================================================================
// Out-proj: out = concat(g_o) @ Wo^T + bo. Same structure as qkv_tc;
// A gathered from [b,h,n,d], bias-add epilogue.
// ===========================================================================
__global__ __launch_bounds__(256) void proj_tc(
    const float* __restrict__ Wo, const float* __restrict__ bo,
    float* __restrict__ outp)
{
    __shared__ __align__(16) uint32_t sA[2][4096];
    __shared__ __align__(16) uint32_t sB[2][2048];

    const int tid = threadIdx.x, lane = tid & 31, wid = tid >> 5;
    const int nx = blockIdx.x, m0 = blockIdx.y * 128;
    const int bb = m0 >> 10, nsb = m0 & 1023;

    const int arow = tid >> 1, ahalf = tid & 1;
    const int brow = tid >> 2, bq = tid & 3;
    const float* Bg = Wo + (size_t)(nx * 64 + brow) * DIM + bq * 8;

    auto aptr = [&](int kt) {
        return g_o + ((size_t)(bb * HEADS + (kt >> 1)) * SEQ + nsb + arow) * DHEAD
               + (kt & 1) * 32 + ahalf * 16;
    };

    float4 pa[4], pb[2];
    {
        const float* ap = aptr(0);
        #pragma unroll
        for (int q = 0; q < 4; q++) pa[q] = *(const float4*)(ap + q * 4);
        #pragma unroll
        for (int q = 0; q < 2; q++) pb[q] = *(const float4*)(Bg + q * 4);
    }

    auto stash = [&](int buf) {
        #pragma unroll
        for (int q = 0; q < 4; q++) {
            int c = ahalf * 4 + q;
            *(uint4*)&sA[buf][arow * 32 + ((c ^ (arow & 7)) << 2)] = rtf4_u(pa[q]);
        }
        #pragma unroll
        for (int q = 0; q < 2; q++) {
            int c = bq * 2 + q;
            *(uint4*)&sB[buf][brow * 32 + ((c ^ (brow & 7)) << 2)] = rtf4_u(pb[q]);
        }
    };

    stash(0);
    __syncthreads();

    const int wm = wid >> 1, wn = wid & 1;
    const uint32_t sAb = smem_u32(sA), sBb = smem_u32(sB);
    const int lx = lane & 7;
    const uint32_t aBase = sAb + (uint32_t)(wm * 32 + (lane & 15)) * 128;
    const int aCsel = lane >> 4;
    const uint32_t bBase = sBb + (uint32_t)(wn * 32 + ((lane >> 4) << 3) + lx) * 128;
    const int bCsel = (lane >> 3) & 1;

    float acc[2][4][4] = {};

    for (int kt = 0; kt < 16; kt++) {
        const int cur = kt & 1;
        if (kt < 15) {
            const float* ap = aptr(kt + 1);
            #pragma unroll
            for (int q = 0; q < 4; q++) pa[q] = *(const float4*)(ap + q * 4);
            #pragma unroll
            for (int q = 0; q < 2; q++) pb[q] = *(const float4*)(Bg + (kt + 1) * 32 + q * 4);
        }
        #pragma unroll
        for (int ik = 0; ik < 4; ik++) {
            uint32_t a[2][4];
            #pragma unroll
            for (int im = 0; im < 2; im++) {
                uint32_t ad = aBase + cur * 16384 + im * 2048
                            + (uint32_t)(((2 * ik + aCsel) ^ lx) << 4);
                LDSM_X4(a[im][0], a[im][1], a[im][2], a[im][3], ad);
            }
            uint32_t b[4][2];
            #pragma unroll
            for (int in2 = 0; in2 < 2; in2++) {
                uint32_t bd = bBase + cur * 8192 + in2 * 2048
                            + (uint32_t)(((2 * ik + bCsel) ^ lx) << 4);
                uint32_t r0, r1, r2, r3;
                LDSM_X4(r0, r1, r2, r3, bd);
                b[in2*2][0] = r0; b[in2*2][1] = r1;
                b[in2*2+1][0] = r2; b[in2*2+1][1] = r3;
            }
            #pragma unroll
            for (int im = 0; im < 2; im++)
                #pragma unroll
                for (int in = 0; in < 4; in++)
                    mma1688(acc[im][in], a[im][0], a[im][1], a[im][2], a[im][3],
                            b[in][0], b[in][1]);
        }
        if (kt < 15) { __syncthreads(); stash((kt + 1) & 1); __syncthreads(); }
    }

    const int g = lane >> 2, tg = lane & 3;
    #pragma unroll
    for (int im = 0; im < 2; im++) {
        #pragma unroll
        for (int in = 0; in < 4; in++) {
            int m = m0 + wm * 32 + im * 16 + g;
            int d = wn * 32 + in * 8 + tg * 2;
            float2 bias = *(const float2*)(bo + nx * 64 + d);
            float* op = outp + (size_t)m * DIM + nx * 64 + d;
            *(float2*)op = make_float2(acc[im][in][0] + bias.x, acc[im][in][1] + bias.y);
            *(float2*)(op + 8 * DIM) = make_float2(acc[im][in][2] + bias.x,
                                                   acc[im][in][3] + bias.y);
        }
    }
}

// ---------------------------------------------------------------------------
extern "C" void kernel_launch(void* const* d_in, const int* in_sizes, int n_in,
                              void* d_out, int out_size)
{
    (void)in_sizes; (void)n_in; (void)out_size;
    const float* x  = (const float*)d_in[0];
    const float* wq = (const float*)d_in[1];
    const float* wk = (const float*)d_in[2];
    const float* wv = (const float*)d_in[3];
    const float* wo = (const float*)d_in[4];
    const float* bo = (const float*)d_in[5];
    float* out = (float*)d_out;

    qkv_tc<<<dim3(HEADS, 64, 3), 256>>>(x, wq, wk, wv);
    attn_tc<<<dim3(16, HEADS, BATCH), 128>>>();
    proj_tc<<<dim3(DIM / 64, 64), 256>>>(wo, bo, out);
}

// round 5
// speedup vs baseline: 6.8601x; 3.0906x over previous
#include <cuda_runtime.h>
#include <cuda_fp16.h>
#include <cstdint>

#define BATCH 8
#define SEQ   1024
#define DIM   512
#define HEADS 8
#define DHEAD 64
#define SCALE 0.125f

#define QKV_ELEMS (BATCH*HEADS*SEQ*DHEAD)

// fp16 staging buffers (device globals: allocation-free rule)
__device__ __half g_xh [8192*512];
__device__ __half g_wqh[512*512];
__device__ __half g_wkh[512*512];
__device__ __half g_wvh[512*512];
__device__ __half g_woh[512*512];
__device__ __half g_q[QKV_ELEMS];
__device__ __half g_k[QKV_ELEMS];
__device__ __half g_v[QKV_ELEMS];
__device__ __half g_o[QKV_ELEMS];

__device__ __forceinline__ uint32_t smem_u32(const void* p) {
    uint32_t a;
    asm("{ .reg .u64 t; cvta.to.shared.u64 t, %1; cvt.u32.u64 %0, t; }" : "=r"(a) : "l"(p));
    return a;
}
// pack (lo, hi) floats -> f16x2
__device__ __forceinline__ uint32_t h2u(float lo, float hi) {
    uint32_t u;
    asm("cvt.rn.f16x2.f32 %0, %1, %2;" : "=r"(u) : "f"(hi), "f"(lo));
    return u;
}

// m16n8k16 fp16 HMMA, fp32 accumulate.
__device__ __forceinline__ void mma16816(float c[4], const uint32_t a[4],
                                         uint32_t b0, uint32_t b1) {
    asm volatile(
        "mma.sync.aligned.m16n8k16.row.col.f32.f16.f16.f32 "
        "{%0,%1,%2,%3}, {%4,%5,%6,%7}, {%8,%9}, {%0,%1,%2,%3};\n"
        : "+f"(c[0]), "+f"(c[1]), "+f"(c[2]), "+f"(c[3])
        : "r"(a[0]), "r"(a[1]), "r"(a[2]), "r"(a[3]), "r"(b0), "r"(b1));
}

#define LDSM_X4(d0, d1, d2, d3, addr) \
    asm volatile("ldmatrix.sync.aligned.m8n8.x4.shared.b16 {%0,%1,%2,%3}, [%4];" \
                 : "=r"(d0), "=r"(d1), "=r"(d2), "=r"(d3) : "r"(addr))
#define LDSM_X4_T(d0, d1, d2, d3, addr) \
    asm volatile("ldmatrix.sync.aligned.m8n8.x4.trans.shared.b16 {%0,%1,%2,%3}, [%4];" \
                 : "=r"(d0), "=r"(d1), "=r"(d2), "=r"(d3) : "r"(addr))

#define CP16(dst, src) \
    asm volatile("cp.async.cg.shared.global [%0], [%1], 16;" :: "r"(dst), "l"(src))
#define CP_COMMIT() asm volatile("cp.async.commit_group;")
#define CP_WAIT0()  asm volatile("cp.async.wait_group 0;")
#define CP_WAIT1()  asm volatile("cp.async.wait_group 1;")

// ---------------------------------------------------------------------------
// Convert fp32 inputs -> fp16 staging. 1310720 float4s total.
// ---------------------------------------------------------------------------
__global__ __launch_bounds__(256) void conv_k(
    const float* __restrict__ x,  const float* __restrict__ wq,
    const float* __restrict__ wk, const float* __restrict__ wv,
    const float* __restrict__ wo)
{
    const uint32_t i = blockIdx.x * 256 + threadIdx.x;   // float4 index
    const float* src; __half* dst; uint32_t off;
    if (i < 1048576u)      { src = x;  dst = g_xh;  off = i; }
    else if (i < 1114112u) { src = wq; dst = g_wqh; off = i - 1048576u; }
    else if (i < 1179648u) { src = wk; dst = g_wkh; off = i - 1114112u; }
    else if (i < 1245184u) { src = wv; dst = g_wvh; off = i - 1179648u; }
    else                   { src = wo; dst = g_woh; off = i - 1245184u; }
    float4 v = ((const float4*)src)[off];
    ((uint2*)dst)[off] = make_uint2(h2u(v.x, v.y), h2u(v.z, v.w));
}

// ---------------------------------------------------------------------------
// QKV: C = X @ W^T scattered to [b,h,n,d] (fp16 out). CTA 128m x 128n (2
// heads), 256 thr (8 warps: 4m x 2n, warp 32x64), k-block 64, cp.async
// double-buffered. smem rows 128B, XOR-8 swizzle, ldmatrix frags.
// ---------------------------------------------------------------------------
__global__ __launch_bounds__(256) void qkv_tc()
{
    extern __shared__ char dsm[];
    const uint32_t sb = smem_u32(dsm);     // A: buf*16384 ; B: 32768 + buf*16384
    const int tid = threadIdx.x, lane = tid & 31, wid = tid >> 5;
    const int nblk = blockIdx.x, m0 = blockIdx.y * 128, z = blockIdx.z;
    const __half* Wh = (z == 0) ? g_wqh : (z == 1) ? g_wkh : g_wvh;
    __half* out = (z == 0) ? g_q : (z == 1) ? g_k : g_v;

    const int arow = tid >> 1, cb = (tid & 1) * 4;
    const __half* asrc = g_xh + (size_t)(m0 + arow) * DIM + cb * 8;
    const __half* bsrc = Wh + (size_t)(nblk * 128 + arow) * DIM + cb * 8;
    const uint32_t adst = sb + arow * 128;
    const uint32_t bdst = sb + 32768 + arow * 128;

    auto fill = [&](int kt, int buf) {
        #pragma unroll
        for (int c = 0; c < 4; c++) {
            int cc = cb + c;
            uint32_t sw = (uint32_t)((cc ^ (arow & 7)) << 4);
            CP16(adst + buf * 16384 + sw, asrc + kt * 64 + c * 8);
            CP16(bdst + buf * 16384 + sw, bsrc + kt * 64 + c * 8);
        }
    };
    fill(0, 0); CP_COMMIT();

    const int wm = wid >> 1, wn = wid & 1;
    const int g = lane >> 2, tg = lane & 3;
    const int ar0 = wm * 32 + (lane & 15);
    const int acs = lane >> 4;
    const int br0 = wn * 64 + ((lane >> 4) << 3) + (lane & 7);
    const int bcs = (lane >> 3) & 1;

    float acc[2][8][4] = {};

    for (int kt = 0; kt < 8; kt++) {
        if (kt < 7) { fill(kt + 1, (kt + 1) & 1); CP_COMMIT(); CP_WAIT1(); }
        else        { CP_WAIT0(); }
        __syncthreads();
        const uint32_t abuf = sb + (kt & 1) * 16384;
        const uint32_t bbuf = sb + 32768 + (kt & 1) * 16384;
        #pragma unroll
        for (int ik = 0; ik < 4; ik++) {
            uint32_t a[2][4];
            #pragma unroll
            for (int im = 0; im < 2; im++) {
                int r = ar0 + im * 16;
                uint32_t ad = abuf + r * 128 + (uint32_t)((((2 * ik + acs) ^ (r & 7))) << 4);
                LDSM_X4(a[im][0], a[im][1], a[im][2], a[im][3], ad);
            }
            #pragma unroll
            for (int nt2 = 0; nt2 < 4; nt2++) {
                int r = br0 + nt2 * 16;
                uint32_t bd = bbuf + r * 128 + (uint32_t)((((2 * ik + bcs) ^ (r & 7))) << 4);
                uint32_t b0, b1, b2, b3;
                LDSM_X4(b0, b1, b2, b3, bd);
                #pragma unroll
                for (int im = 0; im < 2; im++) {
                    mma16816(acc[im][2 * nt2],     a[im], b0, b1);
                    mma16816(acc[im][2 * nt2 + 1], a[im], b2, b3);
                }
            }
        }
        __syncthreads();
    }

    const int b = m0 >> 10, ns0 = m0 & 1023;
    const int head = nblk * 2 + wn;
    #pragma unroll
    for (int im = 0; im < 2; im++) {
        int mrow = wm * 32 + im * 16 + g;
        __half* base = out + ((size_t)(b * HEADS + head) * SEQ + ns0 + mrow) * DHEAD;
        #pragma unroll
        for (int nt = 0; nt < 8; nt++) {
            int d = nt * 8 + 2 * tg;
            *(uint32_t*)(base + d)             = h2u(acc[im][nt][0], acc[im][nt][1]);
            *(uint32_t*)(base + 8 * DHEAD + d) = h2u(acc[im][nt][2], acc[im][nt][3]);
        }
    }
}

// ---------------------------------------------------------------------------
// Attention: CTA per (qt, h, b): 64 q-rows, 128 thr (4 warps x 16q).
// Q frags hoisted; K/V cp.async double-buffered; S accums feed PV A-frags
// directly (fp16 C-layout == A-layout); V^T via ldmatrix.trans.
// ---------------------------------------------------------------------------
__global__ __launch_bounds__(128) void attn_tc()
{
    __shared__ __align__(16) char sm[40960];   // Q@0(8K) K@8192(2x8K) V@24576(2x8K)
    const uint32_t sb = smem_u32(sm);
    const int tid = threadIdx.x, lane = tid & 31, wid = tid >> 5;
    const int qt = blockIdx.x, h = blockIdx.y, b = blockIdx.z;
    const __half* Qg = g_q + ((size_t)(b * HEADS + h) * SEQ + qt * 64) * DHEAD;
    const __half* Kg = g_k + ((size_t)(b * HEADS + h) * SEQ) * DHEAD;
    const __half* Vg = g_v + ((size_t)(b * HEADS + h) * SEQ) * DHEAD;

    const int row = tid >> 1, cb = (tid & 1) * 4;
    #pragma unroll
    for (int c = 0; c < 4; c++) {
        int cc = cb + c;
        CP16(sb + row * 128 + ((cc ^ (row & 7)) << 4), Qg + row * 64 + cc * 8);
    }
    CP_COMMIT();
    auto fillKV = [&](int t, int buf) {
        #pragma unroll
        for (int c = 0; c < 4; c++) {
            int cc = cb + c;
            uint32_t sw = row * 128 + ((cc ^ (row & 7)) << 4);
            CP16(sb + 8192 + buf * 8192 + sw,  Kg + (size_t)(t * 64 + row) * 64 + cc * 8);
            CP16(sb + 24576 + buf * 8192 + sw, Vg + (size_t)(t * 64 + row) * 64 + cc * 8);
        }
    };
    fillKV(0, 0); CP_COMMIT();
    CP_WAIT1();                 // Q group done
    __syncthreads();

    const int g = lane >> 2, tg = lane & 3;
    uint32_t qf[4][4];
    {
        int r = wid * 16 + (lane & 15);
        int cs = lane >> 4;
        #pragma unroll
        for (int ik = 0; ik < 4; ik++) {
            uint32_t ad = sb + r * 128 + (uint32_t)(((2 * ik + cs) ^ (r & 7)) << 4);
            LDSM_X4(qf[ik][0], qf[ik][1], qf[ik][2], qf[ik][3], ad);
        }
    }

    const int br0 = ((lane >> 4) << 3) + (lane & 7);       // K: rows = j
    const int bcs = (lane >> 3) & 1;
    const int vr0 = ((lane >> 3) & 1) * 8 + (lane & 7);    // V trans: rows = j
    const int vcs = lane >> 4;

    float oc[8][4] = {};
    float rsum0 = 0.f, rsum1 = 0.f;

    for (int t = 0; t < 16; t++) {
        if (t < 15) { fillKV(t + 1, (t + 1) & 1); CP_COMMIT(); CP_WAIT1(); }
        else        { CP_WAIT0(); }
        __syncthreads();
        const uint32_t kb = sb + 8192 + (t & 1) * 8192;
        const uint32_t vb = sb + 24576 + (t & 1) * 8192;

        // S = Q K^T
        float sc[8][4] = {};
        #pragma unroll
        for (int ik = 0; ik < 4; ik++) {
            #pragma unroll
            for (int nt2 = 0; nt2 < 4; nt2++) {
                int r = nt2 * 16 + br0;
                uint32_t bd = kb + r * 128 + (uint32_t)(((2 * ik + bcs) ^ (r & 7)) << 4);
                uint32_t b0, b1, b2, b3;
                LDSM_X4(b0, b1, b2, b3, bd);
                mma16816(sc[2 * nt2],     qf[ik], b0, b1);
                mma16816(sc[2 * nt2 + 1], qf[ik], b2, b3);
            }
        }

        // P = exp(clip(S*scale)), running row sums
        #pragma unroll
        for (int in = 0; in < 8; in++) {
            #pragma unroll
            for (int r = 0; r < 4; r++)
                sc[in][r] = __expf(fminf(fmaxf(sc[in][r] * SCALE, 1e-6f), 1.0f));
            rsum0 += sc[in][0] + sc[in][1];
            rsum1 += sc[in][2] + sc[in][3];
        }

        // O += P V : A frags = cvt(sc) (C-layout == A-layout), B via ldmatrix.trans
        #pragma unroll
        for (int jk = 0; jk < 4; jk++) {
            uint32_t a[4];
            a[0] = h2u(sc[2 * jk][0],     sc[2 * jk][1]);
            a[1] = h2u(sc[2 * jk][2],     sc[2 * jk][3]);
            a[2] = h2u(sc[2 * jk + 1][0], sc[2 * jk + 1][1]);
            a[3] = h2u(sc[2 * jk + 1][2], sc[2 * jk + 1][3]);
            #pragma unroll
            for (int dt2 = 0; dt2 < 4; dt2++) {
                int r = jk * 16 + vr0;
                uint32_t bd = vb + r * 128 + (uint32_t)(((2 * dt2 + vcs) ^ (r & 7)) << 4);
                uint32_t b0, b1, b2, b3;
                LDSM_X4_T(b0, b1, b2, b3, bd);
                mma16816(oc[2 * dt2],     a, b0, b1);
                mma16816(oc[2 * dt2 + 1], a, b2, b3);
            }
        }
        __syncthreads();
    }

    rsum0 += __shfl_xor_sync(0xffffffffu, rsum0, 1);
    rsum0 += __shfl_xor_sync(0xffffffffu, rsum0, 2);
    rsum1 += __shfl_xor_sync(0xffffffffu, rsum1, 1);
    rsum1 += __shfl_xor_sync(0xffffffffu, rsum1, 2);
    const float inv0 = 1.0f / rsum0, inv1 = 1.0f / rsum1;

    __half* ob = g_o + ((size_t)(b * HEADS + h) * SEQ + qt * 64 + wid * 16 + g) * DHEAD;
    #pragma unroll
    for (int dt = 0; dt < 8; dt++) {
        int d = dt * 8 + 2 * tg;
        *(uint32_t*)(ob + d)             = h2u(oc[dt][0] * inv0, oc[dt][1] * inv0);
        *(uint32_t*)(ob + 8 * DHEAD + d) = h2u(oc[dt][2] * inv1, oc[dt][3] * inv1);
    }
}

// ---------------------------------------------------------------------------
// Out-proj: out = concat(g_o) @ Wo^T + bo (fp32 out). Same structure as qkv;
// A gathered from [b,h,n,d] fp16 (k-block == one head), bias epilogue.
// ---------------------------------------------------------------------------
__global__ __launch_bounds__(256) void proj_tc(
    const float* __restrict__ bo, float* __restrict__ outp)
{
    extern __shared__ char dsm[];
    const uint32_t sb = smem_u32(dsm);
    const int tid = threadIdx.x, lane = tid & 31, wid = tid >> 5;
    const int nblk = blockIdx.x, m0 = blockIdx.y * 128;
    const int b = m0 >> 10, ns0 = m0 & 1023;

    const int arow = tid >> 1, cb = (tid & 1) * 4;
    const __half* bsrc = g_woh + (size_t)(nblk * 128 + arow) * DIM + cb * 8;
    const uint32_t adst = sb + arow * 128;
    const uint32_t bdst = sb + 32768 + arow * 128;

    auto fill = [&](int kt, int buf) {
        const __half* asrc = g_o + ((size_t)(b * HEADS + kt) * SEQ + ns0 + arow) * DHEAD + cb * 8;
        #pragma unroll
        for (int c = 0; c < 4; c++) {
            int cc = cb + c;
            uint32_t sw = (uint32_t)((cc ^ (arow & 7)) << 4);
            CP16(adst + buf * 16384 + sw, asrc + c * 8);
            CP16(bdst + buf * 16384 + sw, bsrc + kt * 64 + c * 8);
        }
    };
    fill(0, 0); CP_COMMIT();

    const int wm = wid >> 1, wn = wid & 1;
    const int g = lane >> 2, tg = lane & 3;
    const int ar0 = wm * 32 + (lane & 15);
    const int acs = lane >> 4;
    const int br0 = wn * 64 + ((lane >> 4) << 3) + (lane & 7);
    const int bcs = (lane >> 3) & 1;

    float acc[2][8][4] = {};

    for (int kt = 0; kt < 8; kt++) {
        if (kt < 7) { fill(kt + 1, (kt + 1) & 1); CP_COMMIT(); CP_WAIT1(); }
        else        { CP_WAIT0(); }
        __syncthreads();
        const uint32_t abuf = sb + (kt & 1) * 16384;
        const uint32_t bbuf = sb + 32768 + (kt & 1) * 16384;
        #pragma unroll
        for (int ik = 0; ik < 4; ik++) {
            uint32_t a[2][4];
            #pragma unroll
            for (int im = 0; im < 2; im++) {
                int r = ar0 + im * 16;
                uint32_t ad = abuf + r * 128 + (uint32_t)(((2 * ik + acs) ^ (r & 7)) << 4);
                LDSM_X4(a[im][0], a[im][1], a[im][2], a[im][3], ad);
            }
            #pragma unroll
            for (int nt2 = 0; nt2 < 4; nt2++) {
                int r = br0 + nt2 * 16;
                uint32_t bd = bbuf + r * 128 + (uint32_t)(((2 * ik + bcs) ^ (r & 7)) << 4);
                uint32_t b0, b1, b2, b3;
                LDSM_X4(b0, b1, b2, b3, bd);
                #pragma unroll
                for (int im = 0; im < 2; im++) {
                    mma16816(acc[im][2 * nt2],     a[im], b0, b1);
                    mma16816(acc[im][2 * nt2 + 1], a[im], b2, b3);
                }
            }
        }
        __syncthreads();
    }

    #pragma unroll
    for (int im = 0; im < 2; im++) {
        int mrow = m0 + wm * 32 + im * 16 + g;
        #pragma unroll
        for (int nt = 0; nt < 8; nt++) {
            int n = nblk * 128 + wn * 64 + nt * 8 + 2 * tg;
            float2 bias = *(const float2*)(bo + n);
            float* op = outp + (size_t)mrow * DIM + n;
            *(float2*)op = make_float2(acc[im][nt][0] + bias.x, acc[im][nt][1] + bias.y);
            *(float2*)(op + 8 * DIM) = make_float2(acc[im][nt][2] + bias.x,
                                                   acc[im][nt][3] + bias.y);
        }
    }
}

// ---------------------------------------------------------------------------
extern "C" void kernel_launch(void* const* d_in, const int* in_sizes, int n_in,
                              void* d_out, int out_size)
{
    (void)in_sizes; (void)n_in; (void)out_size;
    const float* x  = (const float*)d_in[0];
    const float* wq = (const float*)d_in[1];
    const float* wk = (const float*)d_in[2];
    const float* wv = (const float*)d_in[3];
    const float* wo = (const float*)d_in[4];
    const float* bo = (const float*)d_in[5];
    float* out = (float*)d_out;

    cudaFuncSetAttribute(qkv_tc,  cudaFuncAttributeMaxDynamicSharedMemorySize, 65536);
    cudaFuncSetAttribute(proj_tc, cudaFuncAttributeMaxDynamicSharedMemorySize, 65536);

    conv_k<<<5120, 256>>>(x, wq, wk, wv, wo);
    qkv_tc<<<dim3(4, 64, 3), 256, 65536>>>();
    attn_tc<<<dim3(16, HEADS, BATCH), 128>>>();
    proj_tc<<<dim3(4, 64), 256, 65536>>>(bo, out);
}

// round 6
// speedup vs baseline: 7.2533x; 1.0573x over previous
#include <cuda_runtime.h>
#include <cuda_fp16.h>
#include <cstdint>

#define BATCH 8
#define SEQ   1024
#define DIM   512
#define HEADS 8
#define DHEAD 64
#define SCALE 0.125f

#define QKV_ELEMS (BATCH*HEADS*SEQ*DHEAD)

// fp16 staging buffers (device globals: allocation-free rule)
__device__ __half g_xh [8192*512];
__device__ __half g_wqh[512*512];
__device__ __half g_wkh[512*512];
__device__ __half g_wvh[512*512];
__device__ __half g_woh[512*512];
__device__ __half g_q[QKV_ELEMS];
__device__ __half g_k[QKV_ELEMS];
__device__ __half g_v[QKV_ELEMS];
__device__ __half g_o[QKV_ELEMS];

__device__ __forceinline__ uint32_t smem_u32(const void* p) {
    uint32_t a;
    asm("{ .reg .u64 t; cvta.to.shared.u64 t, %1; cvt.u32.u64 %0, t; }" : "=r"(a) : "l"(p));
    return a;
}
__device__ __forceinline__ uint32_t h2u(float lo, float hi) {
    uint32_t u;
    asm("cvt.rn.f16x2.f32 %0, %1, %2;" : "=r"(u) : "f"(hi), "f"(lo));
    return u;
}

__device__ __forceinline__ void mma16816(float c[4], const uint32_t a[4],
                                         uint32_t b0, uint32_t b1) {
    asm volatile(
        "mma.sync.aligned.m16n8k16.row.col.f32.f16.f16.f32 "
        "{%0,%1,%2,%3}, {%4,%5,%6,%7}, {%8,%9}, {%0,%1,%2,%3};\n"
        : "+f"(c[0]), "+f"(c[1]), "+f"(c[2]), "+f"(c[3])
        : "r"(a[0]), "r"(a[1]), "r"(a[2]), "r"(a[3]), "r"(b0), "r"(b1));
}

#define LDSM_X4(d0, d1, d2, d3, addr) \
    asm volatile("ldmatrix.sync.aligned.m8n8.x4.shared.b16 {%0,%1,%2,%3}, [%4];" \
                 : "=r"(d0), "=r"(d1), "=r"(d2), "=r"(d3) : "r"(addr))
#define LDSM_X4_T(d0, d1, d2, d3, addr) \
    asm volatile("ldmatrix.sync.aligned.m8n8.x4.trans.shared.b16 {%0,%1,%2,%3}, [%4];" \
                 : "=r"(d0), "=r"(d1), "=r"(d2), "=r"(d3) : "r"(addr))

#define CP16(dst, src) \
    asm volatile("cp.async.cg.shared.global [%0], [%1], 16;" :: "r"(dst), "l"(src))
#define CP_COMMIT() asm volatile("cp.async.commit_group;")
#define CP_WAIT1()  asm volatile("cp.async.wait_group 1;")

// ---------------------------------------------------------------------------
// Convert fp32 inputs -> fp16 staging. 1310720 float4s total.
// ---------------------------------------------------------------------------
__global__ __launch_bounds__(256) void conv_k(
    const float* __restrict__ x,  const float* __restrict__ wq,
    const float* __restrict__ wk, const float* __restrict__ wv,
    const float* __restrict__ wo)
{
    const uint32_t i = blockIdx.x * 256 + threadIdx.x;
    const float* src; __half* dst; uint32_t off;
    if (i < 1048576u)      { src = x;  dst = g_xh;  off = i; }
    else if (i < 1114112u) { src = wq; dst = g_wqh; off = i - 1048576u; }
    else if (i < 1179648u) { src = wk; dst = g_wkh; off = i - 1114112u; }
    else if (i < 1245184u) { src = wv; dst = g_wvh; off = i - 1179648u; }
    else                   { src = wo; dst = g_woh; off = i - 1245184u; }
    float4 v = ((const float4*)src)[off];
    ((uint2*)dst)[off] = make_uint2(h2u(v.x, v.y), h2u(v.z, v.w));
}

// ===========================================================================
// QKV: C = X @ W^T scattered to [b,h,n,d] (fp16). CTA 128m x 128n, 256 thr
// (8 warps 4m x 2n), k-block 64, 3-stage cp.async, 1 barrier/iter.
// smem: A 3x16KB @0 ; B 3x16KB @49152. 96KB dynamic.
// ===========================================================================
__global__ __launch_bounds__(256) void qkv_tc()
{
    extern __shared__ char dsm[];
    const uint32_t sb = smem_u32(dsm);
    const int tid = threadIdx.x, lane = tid & 31, wid = tid >> 5;
    const int nblk = blockIdx.x, m0 = blockIdx.y * 128, z = blockIdx.z;
    const __half* Wh = (z == 0) ? g_wqh : (z == 1) ? g_wkh : g_wvh;
    __half* out = (z == 0) ? g_q : (z == 1) ? g_k : g_v;

    const int arow = tid >> 1, cb = (tid & 1) * 4;
    const __half* asrc = g_xh + (size_t)(m0 + arow) * DIM + cb * 8;
    const __half* bsrc = Wh + (size_t)(nblk * 128 + arow) * DIM + cb * 8;
    const uint32_t adst = sb + arow * 128;
    const uint32_t bdst = sb + 49152 + arow * 128;

    auto fill = [&](int kt) {
        const int buf = kt % 3;
        #pragma unroll
        for (int c = 0; c < 4; c++) {
            int cc = cb + c;
            uint32_t sw = (uint32_t)((cc ^ (arow & 7)) << 4);
            CP16(adst + buf * 16384 + sw, asrc + kt * 64 + c * 8);
            CP16(bdst + buf * 16384 + sw, bsrc + kt * 64 + c * 8);
        }
    };
    fill(0); CP_COMMIT();
    fill(1); CP_COMMIT();

    const int wm = wid >> 1, wn = wid & 1;
    const int g = lane >> 2, tg = lane & 3;
    const int ar0 = wm * 32 + (lane & 15);
    const int acs = lane >> 4;
    const int br0 = wn * 64 + ((lane >> 4) << 3) + (lane & 7);
    const int bcs = (lane >> 3) & 1;

    float acc[2][8][4] = {};

    for (int kt = 0; kt < 8; kt++) {
        CP_WAIT1();
        __syncthreads();
        const uint32_t abuf = sb + (kt % 3) * 16384;
        const uint32_t bbuf = sb + 49152 + (kt % 3) * 16384;
        #pragma unroll
        for (int ik = 0; ik < 4; ik++) {
            uint32_t a[2][4];
            #pragma unroll
            for (int im = 0; im < 2; im++) {
                int r = ar0 + im * 16;
                uint32_t ad = abuf + r * 128 + (uint32_t)(((2 * ik + acs) ^ (r & 7)) << 4);
                LDSM_X4(a[im][0], a[im][1], a[im][2], a[im][3], ad);
            }
            #pragma unroll
            for (int nt2 = 0; nt2 < 4; nt2++) {
                int r = br0 + nt2 * 16;
                uint32_t bd = bbuf + r * 128 + (uint32_t)(((2 * ik + bcs) ^ (r & 7)) << 4);
                uint32_t b0, b1, b2, b3;
                LDSM_X4(b0, b1, b2, b3, bd);
                #pragma unroll
                for (int im = 0; im < 2; im++) {
                    mma16816(acc[im][2 * nt2],     a[im], b0, b1);
                    mma16816(acc[im][2 * nt2 + 1], a[im], b2, b3);
                }
            }
        }
        if (kt < 6) fill(kt + 2);
        CP_COMMIT();
    }

    const int b = m0 >> 10, ns0 = m0 & 1023;
    const int head = nblk * 2 + wn;
    #pragma unroll
    for (int im = 0; im < 2; im++) {
        int mrow = wm * 32 + im * 16 + g;
        __half* base = out + ((size_t)(b * HEADS + head) * SEQ + ns0 + mrow) * DHEAD;
        #pragma unroll
        for (int nt = 0; nt < 8; nt++) {
            int d = nt * 8 + 2 * tg;
            *(uint32_t*)(base + d)             = h2u(acc[im][nt][0], acc[im][nt][1]);
            *(uint32_t*)(base + 8 * DHEAD + d) = h2u(acc[im][nt][2], acc[im][nt][3]);
        }
    }
}

// ===========================================================================
// Attention: CTA per (qt, h, b): 128 q-rows, 256 thr (8 warps x 16q).
// Q frags hoisted; K/V 3-stage cp.async; PV A-frags direct from S accums;
// V^T via ldmatrix.trans. smem: Q 16KB @0; K 3x8KB @16384; V 3x8KB @40960.
// ===========================================================================
__global__ __launch_bounds__(256) void attn_tc()
{
    extern __shared__ char dsm[];
    const uint32_t sb = smem_u32(dsm);
    const int tid = threadIdx.x, lane = tid & 31, wid = tid >> 5;
    const int qt = blockIdx.x, h = blockIdx.y, b = blockIdx.z;
    const __half* Qg = g_q + ((size_t)(b * HEADS + h) * SEQ + qt * 128) * DHEAD;
    const __half* Kg = g_k + ((size_t)(b * HEADS + h) * SEQ) * DHEAD;
    const __half* Vg = g_v + ((size_t)(b * HEADS + h) * SEQ) * DHEAD;

    // Q fill: 128 rows, 2 thr/row, 4 chunks each
    {
        const int row = tid >> 1, cq = (tid & 1) * 4;
        #pragma unroll
        for (int c = 0; c < 4; c++) {
            int cc = cq + c;
            CP16(sb + row * 128 + ((cc ^ (row & 7)) << 4), Qg + row * 64 + cc * 8);
        }
    }
    // KV fill: 64 rows, 4 thr/row, 2 chunks each per matrix
    const int kvrow = tid >> 2, kvcb = (tid & 3) * 2;
    auto fillKV = [&](int t) {
        const int buf = t % 3;
        #pragma unroll
        for (int c = 0; c < 2; c++) {
            int cc = kvcb + c;
            uint32_t sw = kvrow * 128 + ((cc ^ (kvrow & 7)) << 4);
            CP16(sb + 16384 + buf * 8192 + sw, Kg + (size_t)(t * 64 + kvrow) * 64 + cc * 8);
            CP16(sb + 40960 + buf * 8192 + sw, Vg + (size_t)(t * 64 + kvrow) * 64 + cc * 8);
        }
    };
    fillKV(0); CP_COMMIT();      // group0: Q + KV0
    fillKV(1); CP_COMMIT();      // group1: KV1
    CP_WAIT1();                  // group0 done
    __syncthreads();

    const int g = lane >> 2, tg = lane & 3;
    uint32_t qf[4][4];
    {
        int r = wid * 16 + (lane & 15);
        int cs = lane >> 4;
        #pragma unroll
        for (int ik = 0; ik < 4; ik++) {
            uint32_t ad = sb + r * 128 + (uint32_t)(((2 * ik + cs) ^ (r & 7)) << 4);
            LDSM_X4(qf[ik][0], qf[ik][1], qf[ik][2], qf[ik][3], ad);
        }
    }

    const int br0 = ((lane >> 4) << 3) + (lane & 7);       // K: rows = j
    const int bcs = (lane >> 3) & 1;
    const int vr0 = ((lane >> 3) & 1) * 8 + (lane & 7);    // V trans: rows = j
    const int vcs = lane >> 4;

    float oc[8][4] = {};
    float rsum0 = 0.f, rsum1 = 0.f;

    for (int t = 0; t < 16; t++) {
        if (t) { CP_WAIT1(); __syncthreads(); }
        const uint32_t kb = sb + 16384 + (t % 3) * 8192;
        const uint32_t vb = sb + 40960 + (t % 3) * 8192;

        // S = Q K^T
        float sc[8][4] = {};
        #pragma unroll
        for (int ik = 0; ik < 4; ik++) {
            #pragma unroll
            for (int nt2 = 0; nt2 < 4; nt2++) {
                int r = nt2 * 16 + br0;
                uint32_t bd = kb + r * 128 + (uint32_t)(((2 * ik + bcs) ^ (r & 7)) << 4);
                uint32_t b0, b1, b2, b3;
                LDSM_X4(b0, b1, b2, b3, bd);
                mma16816(sc[2 * nt2],     qf[ik], b0, b1);
                mma16816(sc[2 * nt2 + 1], qf[ik], b2, b3);
            }
        }

        // P = exp(clip(S*scale)), running row sums
        #pragma unroll
        for (int in = 0; in < 8; in++) {
            #pragma unroll
            for (int r = 0; r < 4; r++)
                sc[in][r] = __expf(fminf(fmaxf(sc[in][r] * SCALE, 1e-6f), 1.0f));
            rsum0 += sc[in][0] + sc[in][1];
            rsum1 += sc[in][2] + sc[in][3];
        }

        // O += P V : A frags = cvt(sc) (C-layout == A-layout), B via ldmatrix.trans
        #pragma unroll
        for (int jk = 0; jk < 4; jk++) {
            uint32_t a[4];
            a[0] = h2u(sc[2 * jk][0],     sc[2 * jk][1]);
            a[1] = h2u(sc[2 * jk][2],     sc[2 * jk][3]);
            a[2] = h2u(sc[2 * jk + 1][0], sc[2 * jk + 1][1]);
            a[3] = h2u(sc[2 * jk + 1][2], sc[2 * jk + 1][3]);
            #pragma unroll
            for (int dt2 = 0; dt2 < 4; dt2++) {
                int r = jk * 16 + vr0;
                uint32_t bd = vb + r * 128 + (uint32_t)(((2 * dt2 + vcs) ^ (r & 7)) << 4);
                uint32_t b0, b1, b2, b3;
                LDSM_X4_T(b0, b1, b2, b3, bd);
                mma16816(oc[2 * dt2],     a, b0, b1);
                mma16816(oc[2 * dt2 + 1], a, b2, b3);
            }
        }
        if (t < 14) fillKV(t + 2);
        CP_COMMIT();
    }

    rsum0 += __shfl_xor_sync(0xffffffffu, rsum0, 1);
    rsum0 += __shfl_xor_sync(0xffffffffu, rsum0, 2);
    rsum1 += __shfl_xor_sync(0xffffffffu, rsum1, 1);
    rsum1 += __shfl_xor_sync(0xffffffffu, rsum1, 2);
    const float inv0 = 1.0f / rsum0, inv1 = 1.0f / rsum1;

    __half* ob = g_o + ((size_t)(b * HEADS + h) * SEQ + qt * 128 + wid * 16 + g) * DHEAD;
    #pragma unroll
    for (int dt = 0; dt < 8; dt++) {
        int d = dt * 8 + 2 * tg;
        *(uint32_t*)(ob + d)             = h2u(oc[dt][0] * inv0, oc[dt][1] * inv0);
        *(uint32_t*)(ob + 8 * DHEAD + d) = h2u(oc[dt][2] * inv1, oc[dt][3] * inv1);
    }
}

// ===========================================================================
// Out-proj: out = concat(g_o) @ Wo^T + bo (fp32). 3-stage pipeline.
// ===========================================================================
__global__ __launch_bounds__(256) void proj_tc(
    const float* __restrict__ bo, float* __restrict__ outp)
{
    extern __shared__ char dsm[];
    const uint32_t sb = smem_u32(dsm);
    const int tid = threadIdx.x, lane = tid & 31, wid = tid >> 5;
    const int nblk = blockIdx.x, m0 = blockIdx.y * 128;
    const int b = m0 >> 10, ns0 = m0 & 1023;

    const int arow = tid >> 1, cb = (tid & 1) * 4;
    const __half* bsrc = g_woh + (size_t)(nblk * 128 + arow) * DIM + cb * 8;
    const uint32_t adst = sb + arow * 128;
    const uint32_t bdst = sb + 49152 + arow * 128;

    auto fill = [&](int kt) {
        const int buf = kt % 3;
        const __half* asrc = g_o + ((size_t)(b * HEADS + kt) * SEQ + ns0 + arow) * DHEAD + cb * 8;
        #pragma unroll
        for (int c = 0; c < 4; c++) {
            int cc = cb + c;
            uint32_t sw = (uint32_t)((cc ^ (arow & 7)) << 4);
            CP16(adst + buf * 16384 + sw, asrc + c * 8);
            CP16(bdst + buf * 16384 + sw, bsrc + kt * 64 + c * 8);
        }
    };
    fill(0); CP_COMMIT();
    fill(1); CP_COMMIT();

    const int wm = wid >> 1, wn = wid & 1;
    const int g = lane >> 2, tg = lane & 3;
    const int ar0 = wm * 32 + (lane & 15);
    const int acs = lane >> 4;
    const int br0 = wn * 64 + ((lane >> 4) << 3) + (lane & 7);
    const int bcs = (lane >> 3) & 1;

    float acc[2][8][4] = {};

    for (int kt = 0; kt < 8; kt++) {
        CP_WAIT1();
        __syncthreads();
        const uint32_t abuf = sb + (kt % 3) * 16384;
        const uint32_t bbuf = sb + 49152 + (kt % 3) * 16384;
        #pragma unroll
        for (int ik = 0; ik < 4; ik++) {
            uint32_t a[2][4];
            #pragma unroll
            for (int im = 0; im < 2; im++) {
                int r = ar0 + im * 16;
                uint32_t ad = abuf + r * 128 + (uint32_t)(((2 * ik + acs) ^ (r & 7)) << 4);
                LDSM_X4(a[im][0], a[im][1], a[im][2], a[im][3], ad);
            }
            #pragma unroll
            for (int nt2 = 0; nt2 < 4; nt2++) {
                int r = br0 + nt2 * 16;
                uint32_t bd = bbuf + r * 128 + (uint32_t)(((2 * ik + bcs) ^ (r & 7)) << 4);
                uint32_t b0, b1, b2, b3;
                LDSM_X4(b0, b1, b2, b3, bd);
                #pragma unroll
                for (int im = 0; im < 2; im++) {
                    mma16816(acc[im][2 * nt2],     a[im], b0, b1);
                    mma16816(acc[im][2 * nt2 + 1], a[im], b2, b3);
                }
            }
        }
        if (kt < 6) fill(kt + 2);
        CP_COMMIT();
    }

    #pragma unroll
    for (int im = 0; im < 2; im++) {
        int mrow = m0 + wm * 32 + im * 16 + g;
        #pragma unroll
        for (int nt = 0; nt < 8; nt++) {
            int n = nblk * 128 + wn * 64 + nt * 8 + 2 * tg;
            float2 bias = *(const float2*)(bo + n);
            float* op = outp + (size_t)mrow * DIM + n;
            *(float2*)op = make_float2(acc[im][nt][0] + bias.x, acc[im][nt][1] + bias.y);
            *(float2*)(op + 8 * DIM) = make_float2(acc[im][nt][2] + bias.x,
                                                   acc[im][nt][3] + bias.y);
        }
    }
}

// ---------------------------------------------------------------------------
extern "C" void kernel_launch(void* const* d_in, const int* in_sizes, int n_in,
                              void* d_out, int out_size)
{
    (void)in_sizes; (void)n_in; (void)out_size;
    const float* x  = (const float*)d_in[0];
    const float* wq = (const float*)d_in[1];
    const float* wk = (const float*)d_in[2];
    const float* wv = (const float*)d_in[3];
    const float* wo = (const float*)d_in[4];
    const float* bo = (const float*)d_in[5];
    float* out = (float*)d_out;

    cudaFuncSetAttribute(qkv_tc,  cudaFuncAttributeMaxDynamicSharedMemorySize, 98304);
    cudaFuncSetAttribute(attn_tc, cudaFuncAttributeMaxDynamicSharedMemorySize, 65536);
    cudaFuncSetAttribute(proj_tc, cudaFuncAttributeMaxDynamicSharedMemorySize, 98304);

    conv_k<<<5120, 256>>>(x, wq, wk, wv, wo);
    qkv_tc<<<dim3(4, 64, 3), 256, 98304>>>();
    attn_tc<<<dim3(SEQ / 128, HEADS, BATCH), 256, 65536>>>();
    proj_tc<<<dim3(4, 64), 256, 98304>>>(bo, out);
}